// round 3
// baseline (speedup 1.0000x reference)
#include <cuda_runtime.h>
#include <math.h>

// ---------------------------------------------------------------------------
// Problem constants (fixed by the dataset generator)
// ---------------------------------------------------------------------------
#define PP   1000003u          // prime modulus
#define NN   1000002u          // group order p-1
#define BATCH 4
#define NPATCH 784
#define LVEC 9
#define KKER 16
#define NPIX (BATCH * NPATCH)        // 3136
#define TOTAL (KKER * NPIX)          // 50176
#define DRANGE 9000
#define TSIZE (2 * DRANGE + 1)       // 18001

static __device__ __constant__ unsigned long long kBARR = 18446688733452309587ULL; // floor(2^64/1000003) computed below is overridden at runtime-safe constexpr; see note
// NOTE: we recompute BARR as a compile-time constant expression to be safe:
__device__ __forceinline__ unsigned long long barr_const() {
    return 0xFFFFFFFFFFFFFFFFULL / 1000003ULL;   // == floor(2^64/p) since p !| 2^64
}

// ---------------------------------------------------------------------------
// Scratch (device globals; no dynamic allocation anywhere)
// ---------------------------------------------------------------------------
__device__ int   g_dlog[1000003];                 // value -> signed exponent
__device__ float g_feat1[BATCH * KKER * NPATCH];  // bn1+relu applied  [4,16,28,28]
__device__ float g_x1[BATCH * 16 * 14 * 14];
__device__ float g_x2[BATCH * 32 * 7 * 7];
__device__ float g_x3[BATCH * 64 * 3 * 3];
__device__ float g_h1[BATCH * 128];

// ---------------------------------------------------------------------------
// Modular arithmetic: Barrett reduction, p < 2^20 so a*b < 2^40
// ---------------------------------------------------------------------------
__device__ __forceinline__ unsigned mmul(unsigned a, unsigned b) {
    unsigned long long x = (unsigned long long)a * b;
    unsigned long long q = __umul64hi(x, barr_const());
    unsigned r = (unsigned)x - (unsigned)q * PP;   // true remainder < 2p, fits 32b
    if (r >= PP) r -= PP;
    return r;
}

__device__ __forceinline__ unsigned mpow(unsigned b, unsigned e) {
    unsigned r = 1u;
    while (e) {
        if (e & 1u) r = mmul(r, b);
        b = mmul(b, b);
        e >>= 1;
    }
    return r;
}

// ---------------------------------------------------------------------------
// Integer-input layout detection (int32 / int64 / float32), from ct0 buffer.
// ct0 elements are in [1, p-1]: int32 layout -> words 1,3,5 nonzero;
// int64 layout -> high words zero; float32 bits of values >= 1.0 exceed p.
// ---------------------------------------------------------------------------
__device__ __forceinline__ int detect_layout(const void* ct0) {
    const unsigned* u = (const unsigned*)ct0;
    unsigned w0 = u[0];
    if (w0 >= 1u && w0 < PP) {
        if (u[1] == 0u && u[3] == 0u && u[5] == 0u) return 1;  // int64
        return 0;                                              // int32
    }
    return 2;                                                  // float32
}

__device__ __forceinline__ long long ld_int(const void* ptr, int idx, int lay) {
    if (lay == 0) return (long long)((const int*)ptr)[idx];
    if (lay == 1) return ((const long long*)ptr)[idx];
    return (long long)llrintf(((const float*)ptr)[idx]);
}

// ---------------------------------------------------------------------------
// K0: build the discrete-log lookup table  g^e -> e  for e in [-9000, 9000]
// ---------------------------------------------------------------------------
__global__ void k_table(const void* ct0, const void* gptr) {
    int t = blockIdx.x * blockDim.x + threadIdx.x;
    if (t >= TSIZE) return;
    int lay = detect_layout(ct0);
    unsigned g = (unsigned)ld_int(gptr, 0, lay) % PP;
    int e = t - DRANGE;
    unsigned ee = (e < 0) ? (unsigned)(e + (int)NN) : (unsigned)e;
    unsigned v = mpow(g, ee);
    g_dlog[v] = e;
}

// ---------------------------------------------------------------------------
// K1: IPFE decrypt + dlog + dequant + conv1-bias + bn1 + relu
// one thread per (k, b, patch)
// ---------------------------------------------------------------------------
__global__ void k_decrypt(const void* ct0, const void* cts, const void* y,
                          const void* sky, const float* __restrict__ bias1,
                          const float* __restrict__ bg, const float* __restrict__ bb,
                          const float* __restrict__ bm, const float* __restrict__ bv) {
    int t = blockIdx.x * blockDim.x + threadIdx.x;
    if (t >= TOTAL) return;
    int lay = detect_layout(ct0);
    int k  = t / NPIX;
    int pj = t - k * NPIX;

    unsigned pos = 1u, neg = 1u;
#pragma unroll
    for (int i = 0; i < LVEC; i++) {
        int yi = (int)ld_int(y, k * LVEC + i, lay);
        unsigned ci = (unsigned)ld_int(cts, pj * LVEC + i, lay);
        if (yi > 0)      pos = mmul(pos, mpow(ci, (unsigned)yi));
        else if (yi < 0) neg = mmul(neg, mpow(ci, (unsigned)(-yi)));
    }
    unsigned c0 = (unsigned)ld_int(ct0, pj, lay);
    unsigned sk = (unsigned)ld_int(sky, k, lay);
    unsigned d  = mpow(c0, sk);              // ct0^sk_y
    unsigned tt = mmul(neg, d);              // fold negative-y product into denom
    unsigned ti = mpow(tt, PP - 2u);         // single Fermat inversion
    unsigned val = mmul(pos, ti);            // = g^{<x,y>} mod p

    int e = g_dlog[val];                     // |<x,y>| <= 9000 guaranteed

    float m = (float)e / 10000.0f + bias1[k];
    float s = bg[k] * rsqrtf(bv[k] + 1e-5f);
    float r = (m - bm[k]) * s + bb[k];
    int b = pj / NPATCH, j = pj - b * NPATCH;
    g_feat1[(b * KKER + k) * NPATCH + j] = fmaxf(r, 0.0f);
}

// ---------------------------------------------------------------------------
// K2: 2x2 max-pool  [4,16,28,28] -> [4,16,14,14]
// ---------------------------------------------------------------------------
__global__ void k_pool1() {
    int t = blockIdx.x * blockDim.x + threadIdx.x;
    if (t >= BATCH * 16 * 14 * 14) return;
    int w = t % 14, h = (t / 14) % 14, c = (t / 196) % 16, b = t / (196 * 16);
    const float* in = g_feat1 + (b * 16 + c) * 784;
    int r0 = (2 * h) * 28 + 2 * w;
    float m = fmaxf(fmaxf(in[r0], in[r0 + 1]), fmaxf(in[r0 + 28], in[r0 + 29]));
    g_x1[t] = m;
}

// ---------------------------------------------------------------------------
// K3: conv2(16->32,3x3,pad1) + bias + bn2 + relu + 2x2 pool  -> [4,32,7,7]
// one thread per pooled output; computes the 2x2 pre-pool window
// ---------------------------------------------------------------------------
__global__ void k_conv2(const float* __restrict__ w2, const float* __restrict__ b2,
                        const float* __restrict__ bg, const float* __restrict__ bb,
                        const float* __restrict__ bm, const float* __restrict__ bv) {
    int t = blockIdx.x * blockDim.x + threadIdx.x;
    if (t >= BATCH * 32 * 7 * 7) return;
    int x = t % 7, y = (t / 7) % 7, o = (t / 49) % 32, b = t / (49 * 32);

    float acc[2][2] = {{0.f, 0.f}, {0.f, 0.f}};
    for (int ic = 0; ic < 16; ic++) {
        const float* xin = g_x1 + (b * 16 + ic) * 196;
        const float* wp  = w2 + (o * 16 + ic) * 9;
#pragma unroll
        for (int kh = 0; kh < 3; kh++) {
#pragma unroll
            for (int kw = 0; kw < 3; kw++) {
                float wv = wp[kh * 3 + kw];
#pragma unroll
                for (int dy = 0; dy < 2; dy++) {
                    int ih = 2 * y + dy + kh - 1;
                    if (ih < 0 || ih >= 14) continue;
#pragma unroll
                    for (int dx = 0; dx < 2; dx++) {
                        int iw = 2 * x + dx + kw - 1;
                        if (iw < 0 || iw >= 14) continue;
                        acc[dy][dx] += wv * xin[ih * 14 + iw];
                    }
                }
            }
        }
    }
    float bias = b2[o];
    float s = bg[o] * rsqrtf(bv[o] + 1e-5f);
    float mx = -1e30f;
#pragma unroll
    for (int dy = 0; dy < 2; dy++)
#pragma unroll
        for (int dx = 0; dx < 2; dx++) {
            float v = (acc[dy][dx] + bias - bm[o]) * s + bb[o];
            mx = fmaxf(mx, fmaxf(v, 0.0f));
        }
    g_x2[t] = mx;
}

// ---------------------------------------------------------------------------
// K4: conv3(32->64,3x3,pad1) + bias + bn3 + relu + 2x2 pool  -> [4,64,3,3]
// ---------------------------------------------------------------------------
__global__ void k_conv3(const float* __restrict__ w3, const float* __restrict__ b3,
                        const float* __restrict__ bg, const float* __restrict__ bb,
                        const float* __restrict__ bm, const float* __restrict__ bv) {
    int t = blockIdx.x * blockDim.x + threadIdx.x;
    if (t >= BATCH * 64 * 3 * 3) return;
    int x = t % 3, y = (t / 3) % 3, o = (t / 9) % 64, b = t / (9 * 64);

    float acc[2][2] = {{0.f, 0.f}, {0.f, 0.f}};
    for (int ic = 0; ic < 32; ic++) {
        const float* xin = g_x2 + (b * 32 + ic) * 49;
        const float* wp  = w3 + (o * 32 + ic) * 9;
#pragma unroll
        for (int kh = 0; kh < 3; kh++) {
#pragma unroll
            for (int kw = 0; kw < 3; kw++) {
                float wv = wp[kh * 3 + kw];
#pragma unroll
                for (int dy = 0; dy < 2; dy++) {
                    int ih = 2 * y + dy + kh - 1;
                    if (ih < 0 || ih >= 7) continue;
#pragma unroll
                    for (int dx = 0; dx < 2; dx++) {
                        int iw = 2 * x + dx + kw - 1;
                        if (iw < 0 || iw >= 7) continue;
                        acc[dy][dx] += wv * xin[ih * 7 + iw];
                    }
                }
            }
        }
    }
    float bias = b3[o];
    float s = bg[o] * rsqrtf(bv[o] + 1e-5f);
    float mx = -1e30f;
#pragma unroll
    for (int dy = 0; dy < 2; dy++)
#pragma unroll
        for (int dx = 0; dx < 2; dx++) {
            float v = (acc[dy][dx] + bias - bm[o]) * s + bb[o];
            mx = fmaxf(mx, fmaxf(v, 0.0f));
        }
    g_x3[t] = mx;
}

// ---------------------------------------------------------------------------
// K5: fc1 576->128 + relu
// ---------------------------------------------------------------------------
__global__ void k_fc1(const float* __restrict__ w, const float* __restrict__ bias) {
    int t = blockIdx.x * blockDim.x + threadIdx.x;
    if (t >= BATCH * 128) return;
    int o = t % 128, b = t / 128;
    const float* xr = g_x3 + b * 576;
    const float* wr = w + o * 576;
    float s = 0.f;
#pragma unroll 8
    for (int f = 0; f < 576; f++) s += xr[f] * wr[f];
    g_h1[t] = fmaxf(s + bias[o], 0.0f);
}

// ---------------------------------------------------------------------------
// K6: fc2 128->10
// ---------------------------------------------------------------------------
__global__ void k_fc2(const float* __restrict__ w, const float* __restrict__ bias,
                      float* __restrict__ out) {
    int t = blockIdx.x * blockDim.x + threadIdx.x;
    if (t >= BATCH * 10) return;
    int o = t % 10, b = t / 10;
    const float* hr = g_h1 + b * 128;
    const float* wr = w + o * 128;
    float s = 0.f;
#pragma unroll 8
    for (int f = 0; f < 128; f++) s += hr[f] * wr[f];
    out[b * 10 + o] = s + bias[o];
}

// ---------------------------------------------------------------------------
// Launcher. Input order (setup_inputs dict order):
// 0 ct0, 1 cts, 2 y, 3 sk_y, 4 bias1, 5-8 bn1 g/b/m/v, 9 conv2_w, 10 conv2_b,
// 11-14 bn2, 15 conv3_w, 16 conv3_b, 17-20 bn3, 21 fc1_w, 22 fc1_b,
// 23 fc2_w, 24 fc2_b, 25 g, 26 p
// ---------------------------------------------------------------------------
extern "C" void kernel_launch(void* const* d_in, const int* in_sizes, int n_in,
                              void* d_out, int out_size) {
    (void)in_sizes; (void)n_in; (void)out_size;
    const void* ct0 = d_in[0];
    const void* cts = d_in[1];
    const void* y   = d_in[2];
    const void* sky = d_in[3];
    const float* bias1 = (const float*)d_in[4];
    const float* bn1g = (const float*)d_in[5],  *bn1b = (const float*)d_in[6];
    const float* bn1m = (const float*)d_in[7],  *bn1v = (const float*)d_in[8];
    const float* c2w  = (const float*)d_in[9],  *c2b  = (const float*)d_in[10];
    const float* bn2g = (const float*)d_in[11], *bn2b = (const float*)d_in[12];
    const float* bn2m = (const float*)d_in[13], *bn2v = (const float*)d_in[14];
    const float* c3w  = (const float*)d_in[15], *c3b  = (const float*)d_in[16];
    const float* bn3g = (const float*)d_in[17], *bn3b = (const float*)d_in[18];
    const float* bn3m = (const float*)d_in[19], *bn3v = (const float*)d_in[20];
    const float* f1w  = (const float*)d_in[21], *f1b  = (const float*)d_in[22];
    const float* f2w  = (const float*)d_in[23], *f2b  = (const float*)d_in[24];
    const void* gptr  = d_in[25];
    float* out = (float*)d_out;

    k_table  <<<(TSIZE + 255) / 256, 256>>>(ct0, gptr);
    k_decrypt<<<(TOTAL + 255) / 256, 256>>>(ct0, cts, y, sky, bias1,
                                            bn1g, bn1b, bn1m, bn1v);
    k_pool1  <<<(BATCH * 16 * 14 * 14 + 255) / 256, 256>>>();
    k_conv2  <<<(BATCH * 32 * 7 * 7 + 255) / 256, 256>>>(c2w, c2b, bn2g, bn2b, bn2m, bn2v);
    k_conv3  <<<(BATCH * 64 * 3 * 3 + 255) / 256, 256>>>(c3w, c3b, bn3g, bn3b, bn3m, bn3v);
    k_fc1    <<<2, 256>>>(f1w, f1b);
    k_fc2    <<<1, 64>>>(f2w, f2b, out);
}

// round 4
// speedup vs baseline: 6.0337x; 6.0337x over previous
#include <cuda_runtime.h>
#include <math.h>

// ---------------------------------------------------------------------------
// Problem constants (fixed by the dataset generator)
// ---------------------------------------------------------------------------
#define PP   1000003u          // prime modulus
#define NN   1000002u          // group order p-1
#define BATCH 4
#define NPATCH 784
#define LVEC 9
#define KKER 16
#define NPIX (BATCH * NPATCH)        // 3136
#define TOTAL (KKER * NPIX)          // 50176
#define DRANGE 9000
#define TSIZE (2 * DRANGE + 1)       // 18001
#define PREP_TOTAL (TSIZE + NPIX * LVEC)   // 18001 + 28224 = 46225

// ---------------------------------------------------------------------------
// Montgomery constants (computed at compile time)
// ---------------------------------------------------------------------------
constexpr unsigned nprime_f() {            // -p^{-1} mod 2^32 (Newton)
    unsigned inv = PP;
    for (int i = 0; i < 5; i++) inv *= 2u - PP * inv;
    return 0u - inv;
}
constexpr unsigned onem_f() { return (unsigned)((1ULL << 32) % PP); }     // R mod p
constexpr unsigned r2_f() {
    return (unsigned)(((unsigned long long)onem_f() * onem_f()) % PP);    // R^2 mod p
}
constexpr unsigned NPRIME = nprime_f();
constexpr unsigned ONEM   = onem_f();
constexpr unsigned R2M    = r2_f();

// ---------------------------------------------------------------------------
// Scratch (device globals; no dynamic allocation anywhere)
// ---------------------------------------------------------------------------
__device__ int      g_dlog[1000003];                     // Mont(g^e) -> e
__device__ unsigned g_ctsM[LVEC * NPIX];                 // Mont(cts),  [i][pixel]
__device__ unsigned g_ctsInvM[LVEC * NPIX];              // Mont(cts^-1)
__device__ __align__(16) float g_feat1[BATCH * KKER * NPATCH];  // bn1+relu [4,16,28,28]
__device__ __align__(16) float g_x2[BATCH * 32 * 7 * 7];
__device__ __align__(16) float g_x3[BATCH * 64 * 3 * 3];
__device__ __align__(16) float g_h1[BATCH * 128];

// ---------------------------------------------------------------------------
// Montgomery multiply: a,b in Mont domain (< p); result < p.  ~6 ALU ops.
// ---------------------------------------------------------------------------
__device__ __forceinline__ unsigned mm(unsigned a, unsigned b) {
    unsigned long long T = (unsigned long long)a * b;
    unsigned m = (unsigned)T * NPRIME;
    unsigned long long t = (T + (unsigned long long)m * PP) >> 32;
    unsigned r = (unsigned)t;
    return (r >= PP) ? r - PP : r;
}

__device__ __forceinline__ unsigned powM(unsigned b, unsigned e) {
    unsigned r = ONEM;
    while (e) {
        if (e & 1u) r = mm(r, b);
        b = mm(b, b);
        e >>= 1;
    }
    return r;
}

// fixed 20-bit exponent pow, fully unrolled (NN-sk < 2^20)
__device__ __forceinline__ unsigned powM20(unsigned b, unsigned e) {
    unsigned r = ONEM;
#pragma unroll
    for (int i = 0; i < 20; i++) {
        if ((e >> i) & 1u) r = mm(r, b);
        b = mm(b, b);
    }
    return r;
}

// ---------------------------------------------------------------------------
// Integer-input layout detection (int32 / int64 / float32), from ct0 buffer.
// ---------------------------------------------------------------------------
__device__ __forceinline__ int detect_layout(const void* ct0) {
    const unsigned* u = (const unsigned*)ct0;
    unsigned w0 = u[0];
    if (w0 >= 1u && w0 < PP) {
        if (u[1] == 0u && u[3] == 0u && u[5] == 0u) return 1;  // int64
        return 0;                                              // int32
    }
    return 2;                                                  // float32
}

__device__ __forceinline__ long long ld_int(const void* ptr, int idx, int lay) {
    if (lay == 0) return (long long)((const int*)ptr)[idx];
    if (lay == 1) return ((const long long*)ptr)[idx];
    return (long long)llrintf(((const float*)ptr)[idx]);
}

// ---------------------------------------------------------------------------
// K0: prep — dlog table (Mont-keyed) + Montgomery cts and cts inverses
// ---------------------------------------------------------------------------
__global__ void k_prep(const void* ct0, const void* cts, const void* gptr) {
    int t = blockIdx.x * blockDim.x + threadIdx.x;
    if (t >= PREP_TOTAL) return;
    int lay = detect_layout(ct0);
    if (t < TSIZE) {
        unsigned g = (unsigned)ld_int(gptr, 0, lay) % PP;
        unsigned gM = mm(g, R2M);
        int e = t - DRANGE;
        unsigned ee = (e < 0) ? (unsigned)(e + (int)NN) : (unsigned)e;
        g_dlog[powM(gM, ee)] = e;
    } else {
        int idx = t - TSIZE;                 // pixel*LVEC + i
        int pix = idx / LVEC, i = idx - pix * LVEC;
        unsigned c = (unsigned)ld_int(cts, idx, lay);
        unsigned cM = mm(c, R2M);
        g_ctsM[i * NPIX + pix]    = cM;
        g_ctsInvM[i * NPIX + pix] = powM(cM, PP - 2u);
    }
}

// ---------------------------------------------------------------------------
// K1: IPFE decrypt (Shamir multi-exp, no inversions) + dlog + bn1 + relu
// ---------------------------------------------------------------------------
__global__ void k_decrypt(const void* ct0, const void* y, const void* sky,
                          const float* __restrict__ bias1,
                          const float* __restrict__ bg, const float* __restrict__ bb,
                          const float* __restrict__ bm, const float* __restrict__ bv) {
    int t = blockIdx.x * blockDim.x + threadIdx.x;
    if (t >= TOTAL) return;
    int lay = detect_layout(ct0);
    int k  = t / NPIX;
    int pj = t - k * NPIX;

    unsigned e[LVEC], base[LVEC];
#pragma unroll
    for (int i = 0; i < LVEC; i++) {
        int yi = (int)ld_int(y, k * LVEC + i, lay);
        e[i] = (unsigned)(yi >= 0 ? yi : -yi);
        base[i] = (yi >= 0) ? g_ctsM[i * NPIX + pj] : g_ctsInvM[i * NPIX + pj];
    }

    // numerator: simultaneous multi-exponentiation over 6-bit |y_i|
    unsigned acc = ONEM;
#pragma unroll
    for (int bit = 5; bit >= 0; --bit) {
        acc = mm(acc, acc);
#pragma unroll
        for (int i = 0; i < LVEC; i++)
            if ((e[i] >> bit) & 1u) acc = mm(acc, base[i]);
    }

    // denominator inverse: ct0^(n - sk)  (independent chain -> ILP with acc)
    unsigned c0  = (unsigned)ld_int(ct0, pj, lay);
    unsigned c0M = mm(c0, R2M);
    unsigned sk  = (unsigned)ld_int(sky, k, lay);
    unsigned d   = powM20(c0M, NN - sk);

    int ev = g_dlog[mm(acc, d)];             // |<x,y>| <= 9000 guaranteed

    float mfl = (float)ev / 10000.0f + bias1[k];
    float s = bg[k] * rsqrtf(bv[k] + 1e-5f);
    float r = (mfl - bm[k]) * s + bb[k];
    int b = pj / NPATCH, j = pj - b * NPATCH;
    g_feat1[(b * KKER + k) * NPATCH + j] = fmaxf(r, 0.0f);
}

// ---------------------------------------------------------------------------
// K2: pool1 + conv2(16->32,3x3,pad1) + bn2 + relu + pool  -> g_x2 [4,32,7,7]
// grid = 4b * 32o = 128 blocks, 196 threads (one per 14x14 pre-pool pixel)
// ---------------------------------------------------------------------------
__global__ void k_conv2f(const float* __restrict__ w2, const float* __restrict__ b2,
                         const float* __restrict__ bg, const float* __restrict__ bb,
                         const float* __restrict__ bm, const float* __restrict__ bv) {
    __shared__ float xs[16 * 196];
    __shared__ float ws[144];
    __shared__ float pre[196];
    int b = blockIdx.x >> 5;
    int o = blockIdx.x & 31;
    int tid = threadIdx.x;            // 0..195
    int h = tid / 14, w = tid % 14;

    // pool1 from g_feat1 (28x28 -> 14x14), all 16 input channels
#pragma unroll
    for (int ch = 0; ch < 16; ch++) {
        const float* in = g_feat1 + (b * 16 + ch) * 784;
        int r0 = (2 * h) * 28 + 2 * w;
        xs[ch * 196 + tid] = fmaxf(fmaxf(in[r0], in[r0 + 1]),
                                   fmaxf(in[r0 + 28], in[r0 + 29]));
    }
    if (tid < 144) ws[tid] = w2[o * 144 + tid];
    __syncthreads();

    float acc = 0.f;
#pragma unroll
    for (int ic = 0; ic < 16; ic++) {
        const float* xp = xs + ic * 196;
        const float* wp = ws + ic * 9;
#pragma unroll
        for (int kh = 0; kh < 3; kh++) {
            int ih = h + kh - 1;
            if (ih < 0 || ih >= 14) continue;
#pragma unroll
            for (int kw = 0; kw < 3; kw++) {
                int iw = w + kw - 1;
                if (iw < 0 || iw >= 14) continue;
                acc += wp[kh * 3 + kw] * xp[ih * 14 + iw];
            }
        }
    }
    float s = bg[o] * rsqrtf(bv[o] + 1e-5f);
    pre[tid] = fmaxf((acc + b2[o] - bm[o]) * s + bb[o], 0.0f);
    __syncthreads();

    if (tid < 49) {
        int py = tid / 7, px = tid % 7;
        int r0 = (2 * py) * 14 + 2 * px;
        g_x2[(b * 32 + o) * 49 + tid] =
            fmaxf(fmaxf(pre[r0], pre[r0 + 1]), fmaxf(pre[r0 + 14], pre[r0 + 15]));
    }
}

// ---------------------------------------------------------------------------
// K3: conv3(32->64,3x3,pad1) + bn3 + relu + pool -> g_x3 [4,64,3,3]
// grid = 4b * 64o = 256 blocks, 64 threads (49 active pre-pool pixels)
// ---------------------------------------------------------------------------
__global__ void k_conv3f(const float* __restrict__ w3, const float* __restrict__ b3,
                         const float* __restrict__ bg, const float* __restrict__ bb,
                         const float* __restrict__ bm, const float* __restrict__ bv) {
    __shared__ float xs[32 * 49];
    __shared__ float ws[288];
    __shared__ float pre[49];
    int b = blockIdx.x >> 6;
    int o = blockIdx.x & 63;
    int tid = threadIdx.x;            // 0..63

    for (int idx = tid; idx < 32 * 49; idx += 64) xs[idx] = g_x2[b * (32 * 49) + idx];
    for (int idx = tid; idx < 288; idx += 64)     ws[idx] = w3[o * 288 + idx];
    __syncthreads();

    if (tid < 49) {
        int h = tid / 7, w = tid % 7;
        float acc = 0.f;
#pragma unroll
        for (int ic = 0; ic < 32; ic++) {
            const float* xp = xs + ic * 49;
            const float* wp = ws + ic * 9;
#pragma unroll
            for (int kh = 0; kh < 3; kh++) {
                int ih = h + kh - 1;
                if (ih < 0 || ih >= 7) continue;
#pragma unroll
                for (int kw = 0; kw < 3; kw++) {
                    int iw = w + kw - 1;
                    if (iw < 0 || iw >= 7) continue;
                    acc += wp[kh * 3 + kw] * xp[ih * 7 + iw];
                }
            }
        }
        float s = bg[o] * rsqrtf(bv[o] + 1e-5f);
        pre[tid] = fmaxf((acc + b3[o] - bm[o]) * s + bb[o], 0.0f);
    }
    __syncthreads();

    if (tid < 9) {
        int py = tid / 3, px = tid % 3;
        int r0 = (2 * py) * 7 + 2 * px;
        g_x3[(b * 64 + o) * 9 + tid] =
            fmaxf(fmaxf(pre[r0], pre[r0 + 1]), fmaxf(pre[r0 + 7], pre[r0 + 8]));
    }
}

// ---------------------------------------------------------------------------
// K4: fc1 576->128 + relu.  grid = 4b * 4og = 16 blocks, 32 threads (1 o each)
// ---------------------------------------------------------------------------
__global__ void k_fc1(const float* __restrict__ w, const float* __restrict__ bias) {
    __shared__ __align__(16) float xs[576];
    int b = blockIdx.x >> 2;
    int o = (blockIdx.x & 3) * 32 + threadIdx.x;
    for (int i = threadIdx.x; i < 144; i += 32)
        ((float4*)xs)[i] = ((const float4*)(g_x3 + b * 576))[i];
    __syncthreads();
    const float4* wr = (const float4*)(w + o * 576);
    float s0 = 0.f, s1 = 0.f, s2 = 0.f, s3 = 0.f;
#pragma unroll 4
    for (int i = 0; i < 144; i++) {
        float4 wv = wr[i];
        float4 xv = ((float4*)xs)[i];
        s0 += wv.x * xv.x; s1 += wv.y * xv.y;
        s2 += wv.z * xv.z; s3 += wv.w * xv.w;
    }
    g_h1[b * 128 + o] = fmaxf((s0 + s1) + (s2 + s3) + bias[o], 0.0f);
}

// ---------------------------------------------------------------------------
// K5: fc2 128->10
// ---------------------------------------------------------------------------
__global__ void k_fc2(const float* __restrict__ w, const float* __restrict__ bias,
                      float* __restrict__ out) {
    __shared__ float hs[512];
    int tid = threadIdx.x;
    for (int i = tid; i < 512; i += 64) hs[i] = g_h1[i];
    __syncthreads();
    if (tid < 40) {
        int o = tid % 10, b = tid / 10;
        const float* wr = w + o * 128;
        const float* hr = hs + b * 128;
        float s = 0.f;
#pragma unroll 8
        for (int i = 0; i < 128; i++) s += wr[i] * hr[i];
        out[b * 10 + o] = s + bias[o];
    }
}

// ---------------------------------------------------------------------------
// Launcher. Input order (setup_inputs dict order):
// 0 ct0, 1 cts, 2 y, 3 sk_y, 4 bias1, 5-8 bn1 g/b/m/v, 9 conv2_w, 10 conv2_b,
// 11-14 bn2, 15 conv3_w, 16 conv3_b, 17-20 bn3, 21 fc1_w, 22 fc1_b,
// 23 fc2_w, 24 fc2_b, 25 g, 26 p
// ---------------------------------------------------------------------------
extern "C" void kernel_launch(void* const* d_in, const int* in_sizes, int n_in,
                              void* d_out, int out_size) {
    (void)in_sizes; (void)n_in; (void)out_size;
    const void* ct0 = d_in[0];
    const void* cts = d_in[1];
    const void* y   = d_in[2];
    const void* sky = d_in[3];
    const float* bias1 = (const float*)d_in[4];
    const float* bn1g = (const float*)d_in[5],  *bn1b = (const float*)d_in[6];
    const float* bn1m = (const float*)d_in[7],  *bn1v = (const float*)d_in[8];
    const float* c2w  = (const float*)d_in[9],  *c2b  = (const float*)d_in[10];
    const float* bn2g = (const float*)d_in[11], *bn2b = (const float*)d_in[12];
    const float* bn2m = (const float*)d_in[13], *bn2v = (const float*)d_in[14];
    const float* c3w  = (const float*)d_in[15], *c3b  = (const float*)d_in[16];
    const float* bn3g = (const float*)d_in[17], *bn3b = (const float*)d_in[18];
    const float* bn3m = (const float*)d_in[19], *bn3v = (const float*)d_in[20];
    const float* f1w  = (const float*)d_in[21], *f1b  = (const float*)d_in[22];
    const float* f2w  = (const float*)d_in[23], *f2b  = (const float*)d_in[24];
    const void* gptr  = d_in[25];
    float* out = (float*)d_out;

    k_prep   <<<(PREP_TOTAL + 255) / 256, 256>>>(ct0, cts, gptr);
    k_decrypt<<<(TOTAL + 255) / 256, 256>>>(ct0, y, sky, bias1,
                                            bn1g, bn1b, bn1m, bn1v);
    k_conv2f <<<128, 196>>>(c2w, c2b, bn2g, bn2b, bn2m, bn2v);
    k_conv3f <<<256, 64>>>(c3w, c3b, bn3g, bn3b, bn3m, bn3v);
    k_fc1    <<<16, 32>>>(f1w, f1b);
    k_fc2    <<<1, 64>>>(f2w, f2b, out);
}

// round 7
// speedup vs baseline: 7.3625x; 1.2202x over previous
#include <cuda_runtime.h>
#include <math.h>

// ---------------------------------------------------------------------------
// Problem constants (fixed by the dataset generator)
// ---------------------------------------------------------------------------
#define PP   1000003u          // prime modulus
#define NN   1000002u          // group order p-1
#define BATCH 4
#define NPATCH 784
#define LVEC 9
#define KKER 16
#define NPIX (BATCH * NPATCH)        // 3136
#define TOTAL (KKER * NPIX)          // 50176
#define DRANGE 9000
#define TSIZE (2 * DRANGE + 1)       // 18001
#define PREP_TOTAL (TSIZE + NPIX * LVEC)   // 18001 + 28224 = 46225

// ---------------------------------------------------------------------------
// Montgomery constants (computed at compile time)
// ---------------------------------------------------------------------------
constexpr unsigned nprime_f() {            // -p^{-1} mod 2^32 (Newton)
    unsigned inv = PP;
    for (int i = 0; i < 5; i++) inv *= 2u - PP * inv;
    return 0u - inv;
}
constexpr unsigned onem_f() { return (unsigned)((1ULL << 32) % PP); }     // R mod p
constexpr unsigned r2_f() {
    return (unsigned)(((unsigned long long)onem_f() * onem_f()) % PP);    // R^2 mod p
}
constexpr unsigned NPRIME = nprime_f();
constexpr unsigned ONEM   = onem_f();
constexpr unsigned R2M    = r2_f();

// ---------------------------------------------------------------------------
// Scratch (device globals; no dynamic allocation anywhere)
// ---------------------------------------------------------------------------
__device__ int      g_dlog[1000003];                     // Mont(g^e) -> e
__device__ unsigned g_ctsM[LVEC * NPIX];                 // Mont(cts),  [i][pixel]
__device__ unsigned g_ctsInvM[LVEC * NPIX];              // Mont(cts^-1)
__device__ __align__(16) float g_feat1[BATCH * KKER * NPATCH];  // bn1+relu [4,16,28,28]
__device__ __align__(16) float g_x2[BATCH * 32 * 7 * 7];
__device__ __align__(16) float g_x3[BATCH * 64 * 3 * 3];

// ---------------------------------------------------------------------------
// Montgomery multiply: a,b in Mont domain (< p); result < p.
// ---------------------------------------------------------------------------
__device__ __forceinline__ unsigned mm(unsigned a, unsigned b) {
    unsigned long long T = (unsigned long long)a * b;
    unsigned m = (unsigned)T * NPRIME;
    unsigned long long t = (T + (unsigned long long)m * PP) >> 32;
    unsigned r = (unsigned)t;
    return (r >= PP) ? r - PP : r;
}

__device__ __forceinline__ unsigned powM(unsigned b, unsigned e) {
    unsigned r = ONEM;
    while (e) {
        if (e & 1u) r = mm(r, b);
        b = mm(b, b);
        e >>= 1;
    }
    return r;
}

// fixed 20-bit exponent pow, fully unrolled (NN-sk < 2^20)
__device__ __forceinline__ unsigned powM20(unsigned b, unsigned e) {
    unsigned r = ONEM;
#pragma unroll
    for (int i = 0; i < 20; i++) {
        if ((e >> i) & 1u) r = mm(r, b);
        b = mm(b, b);
    }
    return r;
}

// ---------------------------------------------------------------------------
// Integer-input layout detection (int32 / int64 / float32), from ct0 buffer.
// ---------------------------------------------------------------------------
__device__ __forceinline__ int detect_layout(const void* ct0) {
    const unsigned* u = (const unsigned*)ct0;
    unsigned w0 = u[0];
    if (w0 >= 1u && w0 < PP) {
        if (u[1] == 0u && u[3] == 0u && u[5] == 0u) return 1;  // int64
        return 0;                                              // int32
    }
    return 2;                                                  // float32
}

__device__ __forceinline__ long long ld_int(const void* ptr, int idx, int lay) {
    if (lay == 0) return (long long)((const int*)ptr)[idx];
    if (lay == 1) return ((const long long*)ptr)[idx];
    return (long long)llrintf(((const float*)ptr)[idx]);
}

// ---------------------------------------------------------------------------
// K0: prep — dlog table (Mont-keyed) + Montgomery cts and cts inverses
// ---------------------------------------------------------------------------
__global__ void k_prep(const void* ct0, const void* cts, const void* gptr) {
    int t = blockIdx.x * blockDim.x + threadIdx.x;
    if (t >= PREP_TOTAL) return;
    int lay = detect_layout(ct0);
    if (t < TSIZE) {
        unsigned g = (unsigned)ld_int(gptr, 0, lay) % PP;
        unsigned gM = mm(g, R2M);
        int e = t - DRANGE;
        unsigned ee = (e < 0) ? (unsigned)(e + (int)NN) : (unsigned)e;
        g_dlog[powM(gM, ee)] = e;
    } else {
        int idx = t - TSIZE;                 // pixel*LVEC + i
        int pix = idx / LVEC, i = idx - pix * LVEC;
        unsigned c = (unsigned)ld_int(cts, idx, lay);
        unsigned cM = mm(c, R2M);
        g_ctsM[i * NPIX + pix]    = cM;
        g_ctsInvM[i * NPIX + pix] = powM(cM, PP - 2u);
    }
}

// ---------------------------------------------------------------------------
// K1: IPFE decrypt (Shamir multi-exp, no inversions) + dlog + bn1 + relu
// ---------------------------------------------------------------------------
__global__ void k_decrypt(const void* ct0, const void* y, const void* sky,
                          const float* __restrict__ bias1,
                          const float* __restrict__ bg, const float* __restrict__ bb,
                          const float* __restrict__ bm, const float* __restrict__ bv) {
    int t = blockIdx.x * blockDim.x + threadIdx.x;
    if (t >= TOTAL) return;
    int lay = detect_layout(ct0);
    int k  = t / NPIX;
    int pj = t - k * NPIX;

    unsigned e[LVEC], base[LVEC];
#pragma unroll
    for (int i = 0; i < LVEC; i++) {
        int yi = (int)ld_int(y, k * LVEC + i, lay);
        e[i] = (unsigned)(yi >= 0 ? yi : -yi);
        base[i] = (yi >= 0) ? g_ctsM[i * NPIX + pj] : g_ctsInvM[i * NPIX + pj];
    }

    // numerator: simultaneous multi-exponentiation over 6-bit |y_i|
    unsigned acc = ONEM;
#pragma unroll
    for (int bit = 5; bit >= 0; --bit) {
        acc = mm(acc, acc);
#pragma unroll
        for (int i = 0; i < LVEC; i++)
            if ((e[i] >> bit) & 1u) acc = mm(acc, base[i]);
    }

    // denominator inverse: ct0^(n - sk)  (independent chain -> ILP with acc)
    unsigned c0  = (unsigned)ld_int(ct0, pj, lay);
    unsigned c0M = mm(c0, R2M);
    unsigned sk  = (unsigned)ld_int(sky, k, lay);
    unsigned d   = powM20(c0M, NN - sk);

    int ev = g_dlog[mm(acc, d)];             // |<x,y>| <= 9000 guaranteed

    float mfl = (float)ev / 10000.0f + bias1[k];
    float s = bg[k] * rsqrtf(bv[k] + 1e-5f);
    float r = (mfl - bm[k]) * s + bb[k];
    int b = pj / NPATCH, j = pj - b * NPATCH;
    g_feat1[(b * KKER + k) * NPATCH + j] = fmaxf(r, 0.0f);
}

// ---------------------------------------------------------------------------
// K2: pool1 + conv2(16->32,3x3,pad1) + bn2 + relu + pool  -> g_x2 [4,32,7,7]
// grid = 4b * 32o = 128 blocks, 392 threads: tid = icg*196 + pix, icg in {0,1}
// each icg group handles 8 input channels; partials reduced in smem.
// ---------------------------------------------------------------------------
__global__ void k_conv2f(const float* __restrict__ w2, const float* __restrict__ b2,
                         const float* __restrict__ bg, const float* __restrict__ bb,
                         const float* __restrict__ bm, const float* __restrict__ bv) {
    __shared__ float xs[16 * 196];      // pooled input, all 16 channels
    __shared__ float ws[144];
    __shared__ float part[2 * 196];
    __shared__ float pre[196];
    int b = blockIdx.x >> 5;
    int o = blockIdx.x & 31;
    int tid = threadIdx.x;              // 0..391
    int icg = tid / 196;                // 0..1
    int pix = tid - icg * 196;          // 0..195
    int h = pix / 14, w = pix % 14;

    // pool1 from g_feat1 (28x28 -> 14x14): 8 channels per icg group
#pragma unroll
    for (int c = 0; c < 8; c++) {
        int ch = icg * 8 + c;
        const float* in = g_feat1 + (b * 16 + ch) * 784;
        int r0 = (2 * h) * 28 + 2 * w;
        xs[ch * 196 + pix] = fmaxf(fmaxf(in[r0], in[r0 + 1]),
                                   fmaxf(in[r0 + 28], in[r0 + 29]));
    }
    if (tid < 144) ws[tid] = w2[o * 144 + tid];
    __syncthreads();

    float acc = 0.f;
#pragma unroll
    for (int c = 0; c < 8; c++) {
        int ic = icg * 8 + c;
        const float* xp = xs + ic * 196;
        const float* wp = ws + ic * 9;
#pragma unroll
        for (int kh = 0; kh < 3; kh++) {
            int ih = h + kh - 1;
            if (ih < 0 || ih >= 14) continue;
#pragma unroll
            for (int kw = 0; kw < 3; kw++) {
                int iw = w + kw - 1;
                if (iw < 0 || iw >= 14) continue;
                acc += wp[kh * 3 + kw] * xp[ih * 14 + iw];
            }
        }
    }
    part[tid] = acc;
    __syncthreads();

    if (tid < 196) {
        float s = bg[o] * rsqrtf(bv[o] + 1e-5f);
        float v = part[tid] + part[196 + tid];
        pre[tid] = fmaxf((v + b2[o] - bm[o]) * s + bb[o], 0.0f);
    }
    __syncthreads();

    if (tid < 49) {
        int py = tid / 7, px = tid % 7;
        int r0 = (2 * py) * 14 + 2 * px;
        g_x2[(b * 32 + o) * 49 + tid] =
            fmaxf(fmaxf(pre[r0], pre[r0 + 1]), fmaxf(pre[r0 + 14], pre[r0 + 15]));
    }
}

// ---------------------------------------------------------------------------
// K3: conv3(32->64,3x3,pad1) + bn3 + relu + pool -> g_x3 [4,64,3,3]
// grid = 4b * 64o = 256 blocks, 196 threads: tid = icg*49 + pix, icg in {0..3}
// each icg group handles 8 of 32 input channels; smem reduce.
// ---------------------------------------------------------------------------
__global__ void k_conv3f(const float* __restrict__ w3, const float* __restrict__ b3,
                         const float* __restrict__ bg, const float* __restrict__ bb,
                         const float* __restrict__ bm, const float* __restrict__ bv) {
    __shared__ float xs[32 * 49];
    __shared__ float ws[288];
    __shared__ float part[4 * 49];
    __shared__ float pre[49];
    int b = blockIdx.x >> 6;
    int o = blockIdx.x & 63;
    int tid = threadIdx.x;              // 0..195
    int icg = tid / 49;                 // 0..3
    int pix = tid - icg * 49;           // 0..48
    int h = pix / 7, w = pix % 7;

#pragma unroll
    for (int r = 0; r < 8; r++) {
        int idx = r * 196 + tid;        // 8*196 = 1568 = 32*49
        xs[idx] = g_x2[b * (32 * 49) + idx];
    }
    if (tid < 144) {
        ws[tid]       = w3[o * 288 + tid];
        ws[tid + 144] = w3[o * 288 + tid + 144];
    }
    __syncthreads();

    float acc = 0.f;
#pragma unroll
    for (int c = 0; c < 8; c++) {
        int ic = icg * 8 + c;
        const float* xp = xs + ic * 49;
        const float* wp = ws + ic * 9;
#pragma unroll
        for (int kh = 0; kh < 3; kh++) {
            int ih = h + kh - 1;
            if (ih < 0 || ih >= 7) continue;
#pragma unroll
            for (int kw = 0; kw < 3; kw++) {
                int iw = w + kw - 1;
                if (iw < 0 || iw >= 7) continue;
                acc += wp[kh * 3 + kw] * xp[ih * 7 + iw];
            }
        }
    }
    part[tid] = acc;
    __syncthreads();

    if (tid < 49) {
        float v = (part[tid] + part[49 + tid]) + (part[98 + tid] + part[147 + tid]);
        float s = bg[o] * rsqrtf(bv[o] + 1e-5f);
        pre[tid] = fmaxf((v + b3[o] - bm[o]) * s + bb[o], 0.0f);
    }
    __syncthreads();

    if (tid < 9) {
        int py = tid / 3, px = tid % 3;
        int r0 = (2 * py) * 7 + 2 * px;
        g_x3[(b * 64 + o) * 9 + tid] =
            fmaxf(fmaxf(pre[r0], pre[r0 + 1]), fmaxf(pre[r0 + 7], pre[r0 + 8]));
    }
}

// ---------------------------------------------------------------------------
// K4: fused fc1(576->128)+relu and fc2(128->10).
// grid = 4 blocks (one per batch image), 128 threads.
// ---------------------------------------------------------------------------
__global__ void k_fc(const float* __restrict__ w1, const float* __restrict__ b1,
                     const float* __restrict__ w2, const float* __restrict__ b2,
                     float* __restrict__ out) {
    __shared__ __align__(16) float xs[576];
    __shared__ float hs[128];
    int b = blockIdx.x;
    int tid = threadIdx.x;              // 0..127 ; o = tid for fc1

    for (int i = tid; i < 144; i += 128)
        ((float4*)xs)[i] = ((const float4*)(g_x3 + b * 576))[i];
    __syncthreads();

    const float4* wr = (const float4*)(w1 + tid * 576);
    float s0 = 0.f, s1 = 0.f, s2 = 0.f, s3 = 0.f;
#pragma unroll 4
    for (int i = 0; i < 144; i++) {
        float4 wv = wr[i];
        float4 xv = ((float4*)xs)[i];
        s0 += wv.x * xv.x; s1 += wv.y * xv.y;
        s2 += wv.z * xv.z; s3 += wv.w * xv.w;
    }
    hs[tid] = fmaxf((s0 + s1) + (s2 + s3) + b1[tid], 0.0f);
    __syncthreads();

    if (tid < 10) {
        const float* wrow = w2 + tid * 128;
        float s = 0.f;
#pragma unroll 8
        for (int i = 0; i < 128; i++) s += wrow[i] * hs[i];
        out[b * 10 + tid] = s + b2[tid];
    }
}

// ---------------------------------------------------------------------------
// Launcher. Input order (setup_inputs dict order):
// 0 ct0, 1 cts, 2 y, 3 sk_y, 4 bias1, 5-8 bn1 g/b/m/v, 9 conv2_w, 10 conv2_b,
// 11-14 bn2, 15 conv3_w, 16 conv3_b, 17-20 bn3, 21 fc1_w, 22 fc1_b,
// 23 fc2_w, 24 fc2_b, 25 g, 26 p
// ---------------------------------------------------------------------------
extern "C" void kernel_launch(void* const* d_in, const int* in_sizes, int n_in,
                              void* d_out, int out_size) {
    (void)in_sizes; (void)n_in; (void)out_size;
    const void* ct0 = d_in[0];
    const void* cts = d_in[1];
    const void* y   = d_in[2];
    const void* sky = d_in[3];
    const float* bias1 = (const float*)d_in[4];
    const float* bn1g = (const float*)d_in[5],  *bn1b = (const float*)d_in[6];
    const float* bn1m = (const float*)d_in[7],  *bn1v = (const float*)d_in[8];
    const float* c2w  = (const float*)d_in[9],  *c2b  = (const float*)d_in[10];
    const float* bn2g = (const float*)d_in[11], *bn2b = (const float*)d_in[12];
    const float* bn2m = (const float*)d_in[13], *bn2v = (const float*)d_in[14];
    const float* c3w  = (const float*)d_in[15], *c3b  = (const float*)d_in[16];
    const float* bn3g = (const float*)d_in[17], *bn3b = (const float*)d_in[18];
    const float* bn3m = (const float*)d_in[19], *bn3v = (const float*)d_in[20];
    const float* f1w  = (const float*)d_in[21], *f1b  = (const float*)d_in[22];
    const float* f2w  = (const float*)d_in[23], *f2b  = (const float*)d_in[24];
    const void* gptr  = d_in[25];
    float* out = (float*)d_out;

    k_prep   <<<(PREP_TOTAL + 255) / 256, 256>>>(ct0, cts, gptr);
    k_decrypt<<<(TOTAL + 255) / 256, 256>>>(ct0, y, sky, bias1,
                                            bn1g, bn1b, bn1m, bn1v);
    k_conv2f <<<128, 392>>>(c2w, c2b, bn2g, bn2b, bn2m, bn2v);
    k_conv3f <<<256, 196>>>(c3w, c3b, bn3g, bn3b, bn3m, bn3v);
    k_fc     <<<4, 128>>>(f1w, f1b, f2w, f2b, out);
}